// round 11
// baseline (speedup 1.0000x reference)
#include <cuda_runtime.h>

#define T_STEPS 4096
#define BATCH 64
#define IN_DIM 4
#define HID 256
#define OUT_DIM 2
#define HALF 128
#define HPAD 132            // 128 floats + 4-float pad (keeps 16B alignment)
#define NBUF 4              // read t&3, write (t+1)&3, wipe (t+2)&3

// hidden-state history for the output head: [T, B, H] fp32 = 268 MB scratch
__device__ float g_hs[(size_t)T_STEPS * BATCH * HID];

__device__ __forceinline__ void fma2(unsigned long long &acc,
                                     unsigned long long a,
                                     unsigned long long b) {
    asm("fma.rn.f32x2 %0, %1, %2, %0;" : "+l"(acc) : "l"(a), "l"(b));
}

__device__ __forceinline__ float2 unpack2(unsigned long long v) {
    float2 f;
    asm("mov.b64 {%0, %1}, %2;" : "=f"(f.x), "=f"(f.y) : "l"(v));
    return f;
}

__device__ __forceinline__ unsigned int smem_u32(const void* p) {
    unsigned int a;
    asm("{ .reg .u64 t; cvta.to.shared.u64 t, %1; cvt.u32.u64 %0, t; }"
        : "=r"(a) : "l"(p));
    return a;
}

__device__ __forceinline__ unsigned int mapa_peer(unsigned int laddr,
                                                  unsigned int peer) {
    unsigned int r;
    asm("mapa.shared::cluster.u32 %0, %1, %2;" : "=r"(r) : "r"(laddr), "r"(peer));
    return r;
}

// 128-MAC dot with NaN-retry. Volatile 16B LDS so each retry re-reads SMEM.
// Unwritten slots hold NaN sentinels -> accumulator NaN -> retry.
// Non-NaN result proves all 128 inputs are real (fresh) data.
__device__ __forceinline__ float dot128_retry(const unsigned long long* __restrict__ wh,
                                              unsigned int a) {
    float part;
    unsigned int bad;
    do {
        unsigned long long c0 = 0ull, c1 = 0ull, c2 = 0ull, c3 = 0ull;
#pragma unroll
        for (int m = 0; m < 32; m += 2) {
            unsigned long long x0, x1, x2, x3;
            asm volatile("ld.volatile.shared.v2.u64 {%0, %1}, [%2];"
                         : "=l"(x0), "=l"(x1) : "r"(a + m * 16));
            asm volatile("ld.volatile.shared.v2.u64 {%0, %1}, [%2];"
                         : "=l"(x2), "=l"(x3) : "r"(a + m * 16 + 16));
            fma2(c0, wh[2 * m],     x0);
            fma2(c1, wh[2 * m + 1], x1);
            fma2(c2, wh[2 * m + 2], x2);
            fma2(c3, wh[2 * m + 3], x3);
        }
        float2 f0 = unpack2(c0), f1 = unpack2(c1);
        float2 f2 = unpack2(c2), f3 = unpack2(c3);
        part = ((f0.x + f0.y) + (f1.x + f1.y)) + ((f2.x + f2.y) + (f3.x + f3.y));
        unsigned int v = __float_as_uint(part);          // fast-math-immune
        bad = ((v & 0x7fffffffu) > 0x7f800000u) ? 1u : 0u;
    } while (__any_sync(0xffffffffu, bad));
    return part;
}

// ---------------------------------------------------------------------------
// Recurrence, output-split, 2-CTA cluster per batch. Barrier-free loop with
// NaN-sentinel self-synchronization (proven in R9/R10). ONE change vs R10:
// pushes are st.RELEASE.cluster — strong stores cannot loiter in the source
// SM's store queue the way weak st.shared::cluster can, attacking the
// ~700cy/step of unexplained data-visibility latency.
// ---------------------------------------------------------------------------
__global__ void __launch_bounds__(256, 1) __cluster_dims__(2, 1, 1)
elman_recurrence(const float* __restrict__ input,
                 const float* __restrict__ Wi,
                 const float* __restrict__ bi,
                 const float* __restrict__ Wh,
                 const float* __restrict__ bh) {
    // hx[buf][khalf][slot]; khalf==rank written locally, 1-rank by peer push
    __shared__ __align__(16) float hx[NBUF][2][HPAD];

    const int tid  = threadIdx.x;
    const int rank = blockIdx.x & 1;
    const int b    = blockIdx.x >> 1;
    const unsigned int peer = rank ^ 1;
    const int jl = tid >> 1;                // output index 0..127
    const int p  = tid & 1;                 // k-half this lane accumulates
    const int jg = HALF * rank + jl;        // global output index

    // --- loop-invariant weights Wh[jg][128p .. +128) in registers ---
    unsigned long long wh[64];
    {
        const ulonglong2* wsrc =
            (const ulonglong2*)(Wh + (size_t)jg * HID + p * HALF);
#pragma unroll
        for (int m = 0; m < 32; ++m) {
            ulonglong2 v = __ldg(wsrc + m);
            wh[2 * m]     = v.x;
            wh[2 * m + 1] = v.y;
        }
    }

    const float4 wi4 = __ldg((const float4*)(Wi + (size_t)jg * IN_DIM));
    const float  cb  = __ldg(bi + jg) + __ldg(bh + jg);

    // --- per-buffer addresses ---
    unsigned int rd_a[NBUF];     // read base:  &hx[s][p][0]
    unsigned int wipe_a[NBUF];   // wipe slot:  &hx[s][p][jl] (this lane's read slot)
    unsigned int wr_a[NBUF];     // local write: &hx[s][rank][jl]   (p==rank lanes)
    unsigned int r_h[NBUF];      // peer push:  peer's &hx[s][rank][jl] (p!=rank)
#pragma unroll
    for (int s = 0; s < NBUF; ++s) {
        rd_a[s]   = smem_u32(&hx[s][p][0]);
        wipe_a[s] = smem_u32(&hx[s][p][jl]);
        wr_a[s]   = smem_u32(&hx[s][rank][jl]);
        r_h[s]    = mapa_peer(smem_u32(&hx[s][rank][jl]), peer);
    }

    // --- init: buffer 0 = h0 = 0 (both halves); buffers 1..3 = all NaN ---
    if (tid < HPAD) {
        hx[0][0][tid] = 0.f;
        hx[0][1][tid] = 0.f;
#pragma unroll
        for (int s = 1; s < NBUF; ++s) {
            ((unsigned int*)&hx[s][0][0])[tid] = 0x7fffffffu;
            ((unsigned int*)&hx[s][1][0])[tid] = 0x7fffffffu;
        }
    }
    __syncthreads();
    // one-time: peer must observe our init before its first pushes land here
    asm volatile("barrier.cluster.arrive.aligned;" ::: "memory");
    asm volatile("barrier.cluster.wait.aligned;" ::: "memory");

    float4 xin = __ldg((const float4*)(input + (size_t)b * IN_DIM));
    float* hsb = g_hs + (size_t)b * HID + (size_t)jg;

    for (int t = 0; t < T_STEPS; ++t) {
        const int cur = t & 3;
        const int nxt = (t + 1) & 3;
        const int wb  = (t + 2) & 3;

        // 1. wipe my read slot in the buffer due for reuse (program order:
        //    precedes my write/push that enables its next producer)
        asm volatile("st.volatile.shared.u32 [%0], %1;"
                     :: "r"(wipe_a[wb]), "r"(0x7fffffffu) : "memory");

        // prefetch next xi (independent of everything)
        float4 xnext = xin;
        if (t + 1 < T_STEPS)
            xnext = __ldg((const float4*)(input +
                          ((size_t)(t + 1) * BATCH + b) * IN_DIM));

        // 2. dot over my k-half; NaN retry self-synchronizes with producers
        float part = dot128_retry(wh, rd_a[cur]);
        // 3. pair reduction + activation
        part += __shfl_xor_sync(0xffffffffu, part, 1);
        float hn = tanhf(part + xin.x * wi4.x + xin.y * wi4.y +
                         xin.z * wi4.z + xin.w * wi4.w + cb);

        // 4. publish h_next (data IS the signal). Remote: STRONG release
        //    store -> prompt drain to the peer's SMEM.
        if (p == rank) {
            asm volatile("st.volatile.shared.u32 [%0], %1;"
                         :: "r"(wr_a[nxt]), "r"(__float_as_uint(hn)) : "memory");
        } else {
            asm volatile("st.release.cluster.shared::cluster.f32 [%0], %1;"
                         :: "r"(r_h[nxt]), "f"(hn) : "memory");
            hsb[(size_t)t * (BATCH * HID)] = hn;   // stream hs (off-path)
        }
        xin = xnext;
        // NO __syncthreads: no STS drain, no barrier latency
    }

    // keep SMEM alive until the peer's last in-flight pushes are irrelevant
    asm volatile("barrier.cluster.arrive.aligned;" ::: "memory");
    asm volatile("barrier.cluster.wait.aligned;" ::: "memory");
}

// ---------------------------------------------------------------------------
// Output head: out[t,b,:] = tanh(hs[t,b,:] @ Wf^T + bf). One warp per row,
// grid-stride; memory-bound (streams 268 MB of hs at ~69% of HBM peak).
// ---------------------------------------------------------------------------
__global__ void __launch_bounds__(256)
elman_head(const float* __restrict__ Wf,
           const float* __restrict__ bf,
           float* __restrict__ out) {
    const int lane   = threadIdx.x & 31;
    const int gwarp  = (blockIdx.x * blockDim.x + threadIdx.x) >> 5;
    const int nwarps = (gridDim.x * blockDim.x) >> 5;

    const float bf0 = __ldg(bf + 0);
    const float bf1 = __ldg(bf + 1);

    const float4* wf0p = (const float4*)(Wf) + lane * 2;
    const float4* wf1p = (const float4*)(Wf + HID) + lane * 2;
    const float4 w00 = __ldg(wf0p), w01 = __ldg(wf0p + 1);
    const float4 w10 = __ldg(wf1p), w11 = __ldg(wf1p + 1);

    const int nrows = T_STEPS * BATCH;
    for (int row = gwarp; row < nrows; row += nwarps) {
        const float4* h = (const float4*)(g_hs + (size_t)row * HID) + lane * 2;
        float4 h0 = h[0], h1 = h[1];
        float s0 = h0.x * w00.x + h0.y * w00.y + h0.z * w00.z + h0.w * w00.w +
                   h1.x * w01.x + h1.y * w01.y + h1.z * w01.z + h1.w * w01.w;
        float s1 = h0.x * w10.x + h0.y * w10.y + h0.z * w10.z + h0.w * w10.w +
                   h1.x * w11.x + h1.y * w11.y + h1.z * w11.z + h1.w * w11.w;
#pragma unroll
        for (int o = 16; o; o >>= 1) {
            s0 += __shfl_xor_sync(0xffffffffu, s0, o);
            s1 += __shfl_xor_sync(0xffffffffu, s1, o);
        }
        if (lane == 0) {
            out[(size_t)row * OUT_DIM + 0] = tanhf(s0 + bf0);
            out[(size_t)row * OUT_DIM + 1] = tanhf(s1 + bf1);
        }
    }
}

// tiny no-op kernel: shifts ncu's capture slot (-s 5 -c 1) so launch #6
// (= 1st graph replay's 2nd launch) is the RECURRENCE kernel, which has
// never been profiled (slot always landed on elman_head with 2 launches).
__global__ void elman_nop() {}

extern "C" void kernel_launch(void* const* d_in, const int* in_sizes, int n_in,
                              void* d_out, int out_size) {
    // metadata order: input, target, Wi, bi, Wh, bh, Wf, bf
    const float* input = (const float*)d_in[0];
    const float* Wi = (const float*)d_in[2];
    const float* bi = (const float*)d_in[3];
    const float* Wh = (const float*)d_in[4];
    const float* bh = (const float*)d_in[5];
    const float* Wf = (const float*)d_in[6];
    const float* bf = (const float*)d_in[7];
    float* out = (float*)d_out;

    elman_nop<<<1, 32>>>();
    elman_recurrence<<<2 * BATCH, 256>>>(input, Wi, bi, Wh, bh);
    elman_head<<<2048, 256>>>(Wf, bf, out);
    elman_nop<<<1, 32>>>();
}

// round 12
// speedup vs baseline: 1.1964x; 1.1964x over previous
#include <cuda_runtime.h>

#define T_STEPS 4096
#define BATCH 64
#define IN_DIM 4
#define HID 256
#define OUT_DIM 2
#define HALF 128
#define HPAD 132            // 128 floats + 4-float pad (keeps 16B alignment)
#define NBUF 4              // read t&3, write (t+1)&3, wipe (t+2)&3

// hidden-state history for the output head: [T, B, H] fp32 = 268 MB scratch
__device__ float g_hs[(size_t)T_STEPS * BATCH * HID];

__device__ __forceinline__ void fma2(unsigned long long &acc,
                                     unsigned long long a,
                                     unsigned long long b) {
    asm("fma.rn.f32x2 %0, %1, %2, %0;" : "+l"(acc) : "l"(a), "l"(b));
}

__device__ __forceinline__ float2 unpack2(unsigned long long v) {
    float2 f;
    asm("mov.b64 {%0, %1}, %2;" : "=f"(f.x), "=f"(f.y) : "l"(v));
    return f;
}

__device__ __forceinline__ unsigned int smem_u32(const void* p) {
    unsigned int a;
    asm("{ .reg .u64 t; cvta.to.shared.u64 t, %1; cvt.u32.u64 %0, t; }"
        : "=r"(a) : "l"(p));
    return a;
}

__device__ __forceinline__ unsigned int mapa_peer(unsigned int laddr,
                                                  unsigned int peer) {
    unsigned int r;
    asm("mapa.shared::cluster.u32 %0, %1, %2;" : "=r"(r) : "r"(laddr), "r"(peer));
    return r;
}

// One 32-MAC chunk: 8 volatile 16B LDS + 16 packed f32x2 FMAs. Returns false
// if any input word is still a NaN sentinel (NaN propagates to the sum).
__device__ __forceinline__ bool chunk32(const unsigned long long* __restrict__ wh,
                                        unsigned int a, float &out) {
    unsigned long long c0 = 0ull, c1 = 0ull, c2 = 0ull, c3 = 0ull;
#pragma unroll
    for (int m = 0; m < 4; ++m) {
        unsigned long long x0, x1, x2, x3;
        asm volatile("ld.volatile.shared.v2.u64 {%0, %1}, [%2];"
                     : "=l"(x0), "=l"(x1) : "r"(a + m * 32));
        asm volatile("ld.volatile.shared.v2.u64 {%0, %1}, [%2];"
                     : "=l"(x2), "=l"(x3) : "r"(a + m * 32 + 16));
        fma2(c0, wh[4 * m],     x0);
        fma2(c1, wh[4 * m + 1], x1);
        fma2(c2, wh[4 * m + 2], x2);
        fma2(c3, wh[4 * m + 3], x3);
    }
    float2 f0 = unpack2(c0), f1 = unpack2(c1);
    float2 f2 = unpack2(c2), f3 = unpack2(c3);
    float s = ((f0.x + f0.y) + (f1.x + f1.y)) + ((f2.x + f2.y) + (f3.x + f3.y));
    unsigned int v = __float_as_uint(s);               // fast-math-immune NaN test
    if ((v & 0x7fffffffu) > 0x7f800000u) return false;
    out = s;
    return true;
}

// 128-MAC dot, chunked NaN-retry: accepted chunks accumulate exactly once;
// only pending chunks re-execute (detect granularity ~1 chunk, not the full
// dot). Per-lane loop, no warp collectives -> lanes with ready data proceed;
// termination guaranteed by the peer's (causally enabled) pushes.
__device__ __forceinline__ float dot128_chunked(const unsigned long long* __restrict__ wh,
                                                unsigned int a) {
    float tot = 0.f;
    unsigned int pend = 0xFu;
    do {
#pragma unroll
        for (int c = 0; c < 4; ++c) {
            if (pend & (1u << c)) {
                float s;
                if (chunk32(wh + 16 * c, a + 128 * c, s)) {
                    tot += s;
                    pend &= ~(1u << c);
                }
            }
        }
    } while (pend);
    return tot;
}

// ---------------------------------------------------------------------------
// Recurrence, output-split, 2-CTA cluster per batch. Barrier-free loop with
// NaN-sentinel self-synchronization (R10 base, the current best). Changes:
//   - pushes back to WEAK st.shared::cluster (R11's release store regressed)
//   - chunked retry dot (finer detect granularity on the arriving half)
// ---------------------------------------------------------------------------
__global__ void __launch_bounds__(256, 1) __cluster_dims__(2, 1, 1)
elman_recurrence(const float* __restrict__ input,
                 const float* __restrict__ Wi,
                 const float* __restrict__ bi,
                 const float* __restrict__ Wh,
                 const float* __restrict__ bh) {
    // hx[buf][khalf][slot]; khalf==rank written locally, 1-rank by peer push
    __shared__ __align__(16) float hx[NBUF][2][HPAD];

    const int tid  = threadIdx.x;
    const int rank = blockIdx.x & 1;
    const int b    = blockIdx.x >> 1;
    const unsigned int peer = rank ^ 1;
    const int jl = tid >> 1;                // output index 0..127
    const int p  = tid & 1;                 // k-half this lane accumulates
    const int jg = HALF * rank + jl;        // global output index

    // --- loop-invariant weights Wh[jg][128p .. +128) in registers ---
    unsigned long long wh[64];
    {
        const ulonglong2* wsrc =
            (const ulonglong2*)(Wh + (size_t)jg * HID + p * HALF);
#pragma unroll
        for (int m = 0; m < 32; ++m) {
            ulonglong2 v = __ldg(wsrc + m);
            wh[2 * m]     = v.x;
            wh[2 * m + 1] = v.y;
        }
    }

    const float4 wi4 = __ldg((const float4*)(Wi + (size_t)jg * IN_DIM));
    const float  cb  = __ldg(bi + jg) + __ldg(bh + jg);

    // --- per-buffer addresses ---
    unsigned int rd_a[NBUF];     // read base:  &hx[s][p][0]
    unsigned int wipe_a[NBUF];   // wipe slot:  &hx[s][p][jl] (this lane's read slot)
    unsigned int wr_a[NBUF];     // local write: &hx[s][rank][jl]   (p==rank lanes)
    unsigned int r_h[NBUF];      // peer push:  peer's &hx[s][rank][jl] (p!=rank)
#pragma unroll
    for (int s = 0; s < NBUF; ++s) {
        rd_a[s]   = smem_u32(&hx[s][p][0]);
        wipe_a[s] = smem_u32(&hx[s][p][jl]);
        wr_a[s]   = smem_u32(&hx[s][rank][jl]);
        r_h[s]    = mapa_peer(smem_u32(&hx[s][rank][jl]), peer);
    }

    // --- init: buffer 0 = h0 = 0 (both halves); buffers 1..3 = all NaN ---
    if (tid < HPAD) {
        hx[0][0][tid] = 0.f;
        hx[0][1][tid] = 0.f;
#pragma unroll
        for (int s = 1; s < NBUF; ++s) {
            ((unsigned int*)&hx[s][0][0])[tid] = 0x7fffffffu;
            ((unsigned int*)&hx[s][1][0])[tid] = 0x7fffffffu;
        }
    }
    __syncthreads();
    // one-time: peer must observe our init before its first pushes land here
    asm volatile("barrier.cluster.arrive.aligned;" ::: "memory");
    asm volatile("barrier.cluster.wait.aligned;" ::: "memory");

    float4 xin = __ldg((const float4*)(input + (size_t)b * IN_DIM));
    float* hsb = g_hs + (size_t)b * HID + (size_t)jg;

    for (int t = 0; t < T_STEPS; ++t) {
        const int cur = t & 3;
        const int nxt = (t + 1) & 3;
        const int wb  = (t + 2) & 3;

        // 1. wipe my read slot in the buffer due for reuse (program order:
        //    precedes my write/push that enables its next producer)
        asm volatile("st.volatile.shared.u32 [%0], %1;"
                     :: "r"(wipe_a[wb]), "r"(0x7fffffffu) : "memory");

        // prefetch next xi (independent of everything)
        float4 xnext = xin;
        if (t + 1 < T_STEPS)
            xnext = __ldg((const float4*)(input +
                          ((size_t)(t + 1) * BATCH + b) * IN_DIM));

        // 2. chunked retry dot over my k-half (self-synchronizing)
        float part = dot128_chunked(wh, rd_a[cur]);
        // 3. pair reduction + activation
        part += __shfl_xor_sync(0xffffffffu, part, 1);
        float hn = tanhf(part + xin.x * wi4.x + xin.y * wi4.y +
                         xin.z * wi4.z + xin.w * wi4.w + cb);

        // 4. publish h_next (data IS the signal) — weak stores (fastest)
        if (p == rank) {
            asm volatile("st.volatile.shared.u32 [%0], %1;"
                         :: "r"(wr_a[nxt]), "r"(__float_as_uint(hn)) : "memory");
        } else {
            asm volatile("st.shared::cluster.f32 [%0], %1;"
                         :: "r"(r_h[nxt]), "f"(hn) : "memory");
            hsb[(size_t)t * (BATCH * HID)] = hn;   // stream hs (off-path)
        }
        xin = xnext;
        // NO __syncthreads in the loop
    }

    // keep SMEM alive until the peer's last in-flight pushes are irrelevant
    asm volatile("barrier.cluster.arrive.aligned;" ::: "memory");
    asm volatile("barrier.cluster.wait.aligned;" ::: "memory");
}

// ---------------------------------------------------------------------------
// Output head: out[t,b,:] = tanh(hs[t,b,:] @ Wf^T + bf). One warp per row,
// grid-stride; memory-bound (streams 268 MB of hs at ~69% of HBM peak).
// ---------------------------------------------------------------------------
__global__ void __launch_bounds__(256)
elman_head(const float* __restrict__ Wf,
           const float* __restrict__ bf,
           float* __restrict__ out) {
    const int lane   = threadIdx.x & 31;
    const int gwarp  = (blockIdx.x * blockDim.x + threadIdx.x) >> 5;
    const int nwarps = (gridDim.x * blockDim.x) >> 5;

    const float bf0 = __ldg(bf + 0);
    const float bf1 = __ldg(bf + 1);

    const float4* wf0p = (const float4*)(Wf) + lane * 2;
    const float4* wf1p = (const float4*)(Wf + HID) + lane * 2;
    const float4 w00 = __ldg(wf0p), w01 = __ldg(wf0p + 1);
    const float4 w10 = __ldg(wf1p), w11 = __ldg(wf1p + 1);

    const int nrows = T_STEPS * BATCH;
    for (int row = gwarp; row < nrows; row += nwarps) {
        const float4* h = (const float4*)(g_hs + (size_t)row * HID) + lane * 2;
        float4 h0 = h[0], h1 = h[1];
        float s0 = h0.x * w00.x + h0.y * w00.y + h0.z * w00.z + h0.w * w00.w +
                   h1.x * w01.x + h1.y * w01.y + h1.z * w01.z + h1.w * w01.w;
        float s1 = h0.x * w10.x + h0.y * w10.y + h0.z * w10.z + h0.w * w10.w +
                   h1.x * w11.x + h1.y * w11.y + h1.z * w11.z + h1.w * w11.w;
#pragma unroll
        for (int o = 16; o; o >>= 1) {
            s0 += __shfl_xor_sync(0xffffffffu, s0, o);
            s1 += __shfl_xor_sync(0xffffffffu, s1, o);
        }
        if (lane == 0) {
            out[(size_t)row * OUT_DIM + 0] = tanhf(s0 + bf0);
            out[(size_t)row * OUT_DIM + 1] = tanhf(s1 + bf1);
        }
    }
}

// nop as the 3rd launch: the harness prepends 2 launches, so ncu's capture
// (skip 5, take #6) lands on OUR 4th launch = the 2nd call's RECURRENCE.
__global__ void elman_nop() {}

extern "C" void kernel_launch(void* const* d_in, const int* in_sizes, int n_in,
                              void* d_out, int out_size) {
    // metadata order: input, target, Wi, bi, Wh, bh, Wf, bf
    const float* input = (const float*)d_in[0];
    const float* Wi = (const float*)d_in[2];
    const float* bi = (const float*)d_in[3];
    const float* Wh = (const float*)d_in[4];
    const float* bh = (const float*)d_in[5];
    const float* Wf = (const float*)d_in[6];
    const float* bf = (const float*)d_in[7];
    float* out = (float*)d_out;

    elman_recurrence<<<2 * BATCH, 256>>>(input, Wi, bi, Wh, bh);
    elman_head<<<2048, 256>>>(Wf, bf, out);
    elman_nop<<<1, 32>>>();
}

// round 13
// speedup vs baseline: 1.3057x; 1.0914x over previous
#include <cuda_runtime.h>

#define T_STEPS 4096
#define BATCH 64
#define IN_DIM 4
#define HID 256
#define OUT_DIM 2
#define HALF 128
#define HPAD 132            // 128 floats + 4-float pad (keeps 16B alignment)
#define NBUF 4              // read t&3, write (t+1)&3, wipe (t+2)&3

// hidden-state history for the output head: [T, B, H] fp32 = 268 MB scratch
__device__ float g_hs[(size_t)T_STEPS * BATCH * HID];

__device__ __forceinline__ void fma2(unsigned long long &acc,
                                     unsigned long long a,
                                     unsigned long long b) {
    asm("fma.rn.f32x2 %0, %1, %2, %0;" : "+l"(acc) : "l"(a), "l"(b));
}

__device__ __forceinline__ float2 unpack2(unsigned long long v) {
    float2 f;
    asm("mov.b64 {%0, %1}, %2;" : "=f"(f.x), "=f"(f.y) : "l"(v));
    return f;
}

__device__ __forceinline__ unsigned int smem_u32(const void* p) {
    unsigned int a;
    asm("{ .reg .u64 t; cvta.to.shared.u64 t, %1; cvt.u32.u64 %0, t; }"
        : "=r"(a) : "l"(p));
    return a;
}

__device__ __forceinline__ unsigned int mapa_peer(unsigned int laddr,
                                                  unsigned int peer) {
    unsigned int r;
    asm("mapa.shared::cluster.u32 %0, %1, %2;" : "=r"(r) : "r"(laddr), "r"(peer));
    return r;
}

// 128-MAC dot with NaN-retry (verify pass). Volatile 16B LDS so each retry
// re-reads SMEM. Non-NaN result proves all 128 inputs are real data.
__device__ __forceinline__ float dot128_retry(const unsigned long long* __restrict__ wh,
                                              unsigned int a) {
    float part;
    unsigned int bad;
    do {
        unsigned long long c0 = 0ull, c1 = 0ull, c2 = 0ull, c3 = 0ull;
#pragma unroll
        for (int m = 0; m < 32; m += 2) {
            unsigned long long x0, x1, x2, x3;
            asm volatile("ld.volatile.shared.v2.u64 {%0, %1}, [%2];"
                         : "=l"(x0), "=l"(x1) : "r"(a + m * 16));
            asm volatile("ld.volatile.shared.v2.u64 {%0, %1}, [%2];"
                         : "=l"(x2), "=l"(x3) : "r"(a + m * 16 + 16));
            fma2(c0, wh[2 * m],     x0);
            fma2(c1, wh[2 * m + 1], x1);
            fma2(c2, wh[2 * m + 2], x2);
            fma2(c3, wh[2 * m + 3], x3);
        }
        float2 f0 = unpack2(c0), f1 = unpack2(c1);
        float2 f2 = unpack2(c2), f3 = unpack2(c3);
        part = ((f0.x + f0.y) + (f1.x + f1.y)) + ((f2.x + f2.y) + (f3.x + f3.y));
        unsigned int v = __float_as_uint(part);          // fast-math-immune
        bad = ((v & 0x7fffffffu) > 0x7f800000u) ? 1u : 0u;
    } while (__any_sync(0xffffffffu, bad));
    return part;
}

// ---------------------------------------------------------------------------
// Recurrence, output-split, 2-CTA cluster per batch. R10 base (current best:
// barrier-free NaN-sentinel fabric, weak pushes) + TWO-PHASE WAIT:
//   phase 1: each lane spins on ONE word — its own slot hx[cur][p][jl] —
//            (1 wavefront/warp/poll). This keeps the SMEM crossbar nearly
//            idle while waiting, so incoming DSMEM stores from the peer do
//            not queue behind poll traffic (the R12 profile showed 30% L1
//            utilization from poll spam = self-inflicted arrival delay).
//   phase 2: monolithic verify dot with NaN retry (catches stragglers).
// ---------------------------------------------------------------------------
__global__ void __launch_bounds__(256, 1) __cluster_dims__(2, 1, 1)
elman_recurrence(const float* __restrict__ input,
                 const float* __restrict__ Wi,
                 const float* __restrict__ bi,
                 const float* __restrict__ Wh,
                 const float* __restrict__ bh) {
    // hx[buf][khalf][slot]; khalf==rank written locally, 1-rank by peer push
    __shared__ __align__(16) float hx[NBUF][2][HPAD];

    const int tid  = threadIdx.x;
    const int rank = blockIdx.x & 1;
    const int b    = blockIdx.x >> 1;
    const unsigned int peer = rank ^ 1;
    const int jl = tid >> 1;                // output index 0..127
    const int p  = tid & 1;                 // k-half this lane accumulates
    const int jg = HALF * rank + jl;        // global output index

    // --- loop-invariant weights Wh[jg][128p .. +128) in registers ---
    unsigned long long wh[64];
    {
        const ulonglong2* wsrc =
            (const ulonglong2*)(Wh + (size_t)jg * HID + p * HALF);
#pragma unroll
        for (int m = 0; m < 32; ++m) {
            ulonglong2 v = __ldg(wsrc + m);
            wh[2 * m]     = v.x;
            wh[2 * m + 1] = v.y;
        }
    }

    const float4 wi4 = __ldg((const float4*)(Wi + (size_t)jg * IN_DIM));
    const float  cb  = __ldg(bi + jg) + __ldg(bh + jg);

    // --- per-buffer addresses ---
    unsigned int rd_a[NBUF];     // read base:  &hx[s][p][0]
    unsigned int spin_a[NBUF];   // spin word:  &hx[s][p][jl]
    unsigned int wr_a[NBUF];     // local write: &hx[s][rank][jl]   (p==rank lanes)
    unsigned int r_h[NBUF];      // peer push:  peer's &hx[s][rank][jl] (p!=rank)
#pragma unroll
    for (int s = 0; s < NBUF; ++s) {
        rd_a[s]   = smem_u32(&hx[s][p][0]);
        spin_a[s] = smem_u32(&hx[s][p][jl]);
        wr_a[s]   = smem_u32(&hx[s][rank][jl]);
        r_h[s]    = mapa_peer(smem_u32(&hx[s][rank][jl]), peer);
    }

    // --- init: buffer 0 = h0 = 0 (both halves); buffers 1..3 = all NaN ---
    if (tid < HPAD) {
        hx[0][0][tid] = 0.f;
        hx[0][1][tid] = 0.f;
#pragma unroll
        for (int s = 1; s < NBUF; ++s) {
            ((unsigned int*)&hx[s][0][0])[tid] = 0x7fffffffu;
            ((unsigned int*)&hx[s][1][0])[tid] = 0x7fffffffu;
        }
    }
    __syncthreads();
    // one-time: peer must observe our init before its first pushes land here
    asm volatile("barrier.cluster.arrive.aligned;" ::: "memory");
    asm volatile("barrier.cluster.wait.aligned;" ::: "memory");

    float4 xin = __ldg((const float4*)(input + (size_t)b * IN_DIM));
    float* hsb = g_hs + (size_t)b * HID + (size_t)jg;

    for (int t = 0; t < T_STEPS; ++t) {
        const int cur = t & 3;
        const int nxt = (t + 1) & 3;
        const int wb  = (t + 2) & 3;

        // 1. wipe my read slot in the buffer due for reuse (program order:
        //    precedes my write/push that enables its next producer)
        asm volatile("st.volatile.shared.u32 [%0], %1;"
                     :: "r"(spin_a[wb]), "r"(0x7fffffffu) : "memory");

        // prefetch next xi (independent of everything)
        float4 xnext = xin;
        if (t + 1 < T_STEPS)
            xnext = __ldg((const float4*)(input +
                          ((size_t)(t + 1) * BATCH + b) * IN_DIM));

        // 2a. PHASE 1: cheap spin on my own slot — minimal SMEM traffic so
        //     the peer's incoming DSMEM stores land without port contention
        {
            unsigned int v;
            do {
                asm volatile("ld.volatile.shared.u32 %0, [%1];"
                             : "=r"(v) : "r"(spin_a[cur]));
            } while ((v & 0x7fffffffu) > 0x7f800000u);
        }
        __syncwarp();

        // 2b. PHASE 2: verify dot with NaN retry (stragglers only)
        float part = dot128_retry(wh, rd_a[cur]);
        // 3. pair reduction + activation
        part += __shfl_xor_sync(0xffffffffu, part, 1);
        float hn = tanhf(part + xin.x * wi4.x + xin.y * wi4.y +
                         xin.z * wi4.z + xin.w * wi4.w + cb);

        // 4. publish h_next (data IS the signal) — weak stores (fastest)
        if (p == rank) {
            asm volatile("st.volatile.shared.u32 [%0], %1;"
                         :: "r"(wr_a[nxt]), "r"(__float_as_uint(hn)) : "memory");
        } else {
            asm volatile("st.shared::cluster.f32 [%0], %1;"
                         :: "r"(r_h[nxt]), "f"(hn) : "memory");
            hsb[(size_t)t * (BATCH * HID)] = hn;   // stream hs (off-path)
        }
        xin = xnext;
        // NO __syncthreads in the loop
    }

    // keep SMEM alive until the peer's last in-flight pushes are irrelevant
    asm volatile("barrier.cluster.arrive.aligned;" ::: "memory");
    asm volatile("barrier.cluster.wait.aligned;" ::: "memory");
}

// ---------------------------------------------------------------------------
// Output head: out[t,b,:] = tanh(hs[t,b,:] @ Wf^T + bf). One warp per row,
// grid-stride; memory-bound (streams 268 MB of hs at ~69% of HBM peak).
// ---------------------------------------------------------------------------
__global__ void __launch_bounds__(256)
elman_head(const float* __restrict__ Wf,
           const float* __restrict__ bf,
           float* __restrict__ out) {
    const int lane   = threadIdx.x & 31;
    const int gwarp  = (blockIdx.x * blockDim.x + threadIdx.x) >> 5;
    const int nwarps = (gridDim.x * blockDim.x) >> 5;

    const float bf0 = __ldg(bf + 0);
    const float bf1 = __ldg(bf + 1);

    const float4* wf0p = (const float4*)(Wf) + lane * 2;
    const float4* wf1p = (const float4*)(Wf + HID) + lane * 2;
    const float4 w00 = __ldg(wf0p), w01 = __ldg(wf0p + 1);
    const float4 w10 = __ldg(wf1p), w11 = __ldg(wf1p + 1);

    const int nrows = T_STEPS * BATCH;
    for (int row = gwarp; row < nrows; row += nwarps) {
        const float4* h = (const float4*)(g_hs + (size_t)row * HID) + lane * 2;
        float4 h0 = h[0], h1 = h[1];
        float s0 = h0.x * w00.x + h0.y * w00.y + h0.z * w00.z + h0.w * w00.w +
                   h1.x * w01.x + h1.y * w01.y + h1.z * w01.z + h1.w * w01.w;
        float s1 = h0.x * w10.x + h0.y * w10.y + h0.z * w10.z + h0.w * w10.w +
                   h1.x * w11.x + h1.y * w11.y + h1.z * w11.z + h1.w * w11.w;
#pragma unroll
        for (int o = 16; o; o >>= 1) {
            s0 += __shfl_xor_sync(0xffffffffu, s0, o);
            s1 += __shfl_xor_sync(0xffffffffu, s1, o);
        }
        if (lane == 0) {
            out[(size_t)row * OUT_DIM + 0] = tanhf(s0 + bf0);
            out[(size_t)row * OUT_DIM + 1] = tanhf(s1 + bf1);
        }
    }
}

// nop as the 3rd launch: the harness prepends 2 launches, so ncu's capture
// (skip 5, take #6) lands on OUR 4th launch = the 2nd call's RECURRENCE.
__global__ void elman_nop() {}

extern "C" void kernel_launch(void* const* d_in, const int* in_sizes, int n_in,
                              void* d_out, int out_size) {
    // metadata order: input, target, Wi, bi, Wh, bh, Wf, bf
    const float* input = (const float*)d_in[0];
    const float* Wi = (const float*)d_in[2];
    const float* bi = (const float*)d_in[3];
    const float* Wh = (const float*)d_in[4];
    const float* bh = (const float*)d_in[5];
    const float* Wf = (const float*)d_in[6];
    const float* bf = (const float*)d_in[7];
    float* out = (float*)d_out;

    elman_recurrence<<<2 * BATCH, 256>>>(input, Wi, bi, Wh, bh);
    elman_head<<<2048, 256>>>(Wf, bf, out);
    elman_nop<<<1, 32>>>();
}